// round 11
// baseline (speedup 1.0000x reference)
#include <cuda_runtime.h>
#include <cuda_bf16.h>
#include <cuda_fp16.h>
#include <cstdint>

// Problem constants
#define BB  2
#define SS  2048
#define DD  1024
#define HH  16
#define DKK 64
#define MM  (BB*SS)   // 4096 rows

#define ELEMS_IN ((size_t)MM*DD)   // 4194304
#define ELEMS_W  ((size_t)DD*DD)   // 1048576

// Offsets (elements) inside the shared hi/lo bf16 scratch
#define OFF_Q  ((size_t)0)
#define OFF_K  (ELEMS_IN)
#define OFF_V  (2*ELEMS_IN)
#define OFF_O  (3*ELEMS_IN)
#define OFF_WQ (4*ELEMS_IN)
#define OFF_WK (4*ELEMS_IN + ELEMS_W)
#define OFF_WV (4*ELEMS_IN + 2*ELEMS_W)
#define OFF_WO (4*ELEMS_IN + 3*ELEMS_W)

// Scratch (allocation-free rule: __device__ globals)
__device__ float g_Q[ELEMS_IN];
__device__ float g_K[ELEMS_IN];
__device__ float g_V[ELEMS_IN];
__device__ float g_O[ELEMS_IN];
__device__ __nv_bfloat16 g_hi[4*ELEMS_IN + 4*ELEMS_W];
__device__ __nv_bfloat16 g_lo[4*ELEMS_IN + 4*ELEMS_W];

// ---------------------------------------------------------------------------
// helpers
// ---------------------------------------------------------------------------
__device__ __forceinline__ uint32_t smem_u32(const void* p) {
    uint32_t a;
    asm("{ .reg .u64 t; cvta.to.shared.u64 t, %1; cvt.u32.u64 %0, t; }"
        : "=r"(a) : "l"(p));
    return a;
}

__device__ __forceinline__ void ldmatrix_x4(uint32_t* r, uint32_t addr) {
    asm volatile("ldmatrix.sync.aligned.m8n8.x4.shared.b16 {%0,%1,%2,%3}, [%4];"
                 : "=r"(r[0]), "=r"(r[1]), "=r"(r[2]), "=r"(r[3]) : "r"(addr));
}

__device__ __forceinline__ void mma_bf16(float* c, const uint32_t* a,
                                         const uint32_t* b) {
    asm volatile(
        "mma.sync.aligned.m16n8k16.row.col.f32.bf16.bf16.f32 "
        "{%0,%1,%2,%3}, {%4,%5,%6,%7}, {%8,%9}, {%0,%1,%2,%3};"
        : "+f"(c[0]), "+f"(c[1]), "+f"(c[2]), "+f"(c[3])
        : "r"(a[0]), "r"(a[1]), "r"(a[2]), "r"(a[3]), "r"(b[0]), "r"(b[1]));
}

__device__ __forceinline__ void mma_f16(float* c, const uint32_t* a,
                                        uint32_t b0, uint32_t b1) {
    asm volatile(
        "mma.sync.aligned.m16n8k16.row.col.f32.f16.f16.f32 "
        "{%0,%1,%2,%3}, {%4,%5,%6,%7}, {%8,%9}, {%0,%1,%2,%3};"
        : "+f"(c[0]), "+f"(c[1]), "+f"(c[2]), "+f"(c[3])
        : "r"(a[0]), "r"(a[1]), "r"(a[2]), "r"(a[3]), "r"(b0), "r"(b1));
}

// ---------------------------------------------------------------------------
// fp32 -> (bf16 hi, bf16 lo) split, vectorized x4.
// ---------------------------------------------------------------------------
__global__ __launch_bounds__(256) void split_bf16(
    const float* __restrict__ in, __nv_bfloat16* __restrict__ hi,
    __nv_bfloat16* __restrict__ lo, int n4)
{
    int i = blockIdx.x * blockDim.x + threadIdx.x;
    if (i >= n4) return;
    float4 a = ((const float4*)in)[i];
    uint32_t b0 = __float_as_uint(a.x), b1 = __float_as_uint(a.y);
    uint32_t b2 = __float_as_uint(a.z), b3 = __float_as_uint(a.w);
    uint2 h;
    h.x = (b0 >> 16) | (b1 & 0xffff0000u);
    h.y = (b2 >> 16) | (b3 & 0xffff0000u);
    float l0 = a.x - __uint_as_float(b0 & 0xffff0000u);
    float l1 = a.y - __uint_as_float(b1 & 0xffff0000u);
    float l2 = a.z - __uint_as_float(b2 & 0xffff0000u);
    float l3 = a.w - __uint_as_float(b3 & 0xffff0000u);
    __nv_bfloat162 p0 = __floats2bfloat162_rn(l0, l1);
    __nv_bfloat162 p1 = __floats2bfloat162_rn(l2, l3);
    uint2 lw;
    lw.x = *(uint32_t*)&p0;
    lw.y = *(uint32_t*)&p1;
    ((uint2*)hi)[i] = h;
    ((uint2*)lo)[i] = lw;
}

// ---------------------------------------------------------------------------
// HMMA bf16x3 GEMM (NT): C[m][n] = sum_k A[m][k]*W[n][k] + bias[n]
// R10: register-prefetch double buffering — next tile's LDGs issue before
// the compute phase so DRAM/L2 latency hides under the 96-MMA stream.
// Math order identical to R6/R9 (bit-exact results).
// ---------------------------------------------------------------------------
#define KSTR 40

__global__ __launch_bounds__(256) void gemm_hmma(
    const __nv_bfloat16* __restrict__ Ahi, const __nv_bfloat16* __restrict__ Alo,
    const __nv_bfloat16* __restrict__ Whi, const __nv_bfloat16* __restrict__ Wlo,
    const float* __restrict__ bias, float* __restrict__ C)
{
    __shared__ __align__(16) __nv_bfloat16 sAh[128 * KSTR], sAl[128 * KSTR];
    __shared__ __align__(16) __nv_bfloat16 sWh[128 * KSTR], sWl[128 * KSTR];

    const int tid  = threadIdx.x;
    const int warp = tid >> 5;
    const int lane = tid & 31;
    const int wm   = warp & 1;
    const int wn   = warp >> 1;
    const int m0   = blockIdx.y * 128;
    const int n0   = blockIdx.x * 128;

    const uint32_t sAh_b = smem_u32(sAh), sAl_b = smem_u32(sAl);
    const uint32_t sWh_b = smem_u32(sWh), sWl_b = smem_u32(sWl);

    float acc[4][4][4] = {};

    const int lrow = tid >> 1;
    const int lcol = (tid & 1) * 16;
    const uint32_t s_off = (uint32_t)(lrow * KSTR + lcol) * 2;

    const int fr = lane & 15;
    const int fc = (lane >> 4) * 8;
    const uint32_t a_off = (uint32_t)((wm * 64 + fr) * KSTR + fc) * 2;
    const uint32_t b_off = (uint32_t)((wn * 32 + fr) * KSTR + fc) * 2;

    const size_t gabase = (size_t)(m0 + lrow) * DD + lcol;
    const size_t gwbase = (size_t)(n0 + lrow) * DD + lcol;

    uint4 pAh0, pAh1, pAl0, pAl1, pWh0, pWh1, pWl0, pWl1;

    // prologue: load k0 = 0
    {
        pAh0 = *(const uint4*)(Ahi + gabase);
        pAh1 = *(const uint4*)(Ahi + gabase + 8);
        pAl0 = *(const uint4*)(Alo + gabase);
        pAl1 = *(const uint4*)(Alo + gabase + 8);
        pWh0 = *(const uint4*)(Whi + gwbase);
        pWh1 = *(const uint4*)(Whi + gwbase + 8);
        pWl0 = *(const uint4*)(Wlo + gwbase);
        pWl1 = *(const uint4*)(Wlo + gwbase + 8);
    }
    *(uint4*)((char*)sAh + s_off)      = pAh0;
    *(uint4*)((char*)sAh + s_off + 16) = pAh1;
    *(uint4*)((char*)sAl + s_off)      = pAl0;
    *(uint4*)((char*)sAl + s_off + 16) = pAl1;
    *(uint4*)((char*)sWh + s_off)      = pWh0;
    *(uint4*)((char*)sWh + s_off + 16) = pWh1;
    *(uint4*)((char*)sWl + s_off)      = pWl0;
    *(uint4*)((char*)sWl + s_off + 16) = pWl1;
    __syncthreads();

    for (int k0 = 0; k0 < DD; k0 += 32) {
        const bool more = (k0 + 32 < DD);
        // prefetch next tile into registers (latency overlaps compute below)
        if (more) {
            const size_t ga = gabase + k0 + 32;
            const size_t gw = gwbase + k0 + 32;
            pAh0 = *(const uint4*)(Ahi + ga);
            pAh1 = *(const uint4*)(Ahi + ga + 8);
            pAl0 = *(const uint4*)(Alo + ga);
            pAl1 = *(const uint4*)(Alo + ga + 8);
            pWh0 = *(const uint4*)(Whi + gw);
            pWh1 = *(const uint4*)(Whi + gw + 8);
            pWl0 = *(const uint4*)(Wlo + gw);
            pWl1 = *(const uint4*)(Wlo + gw + 8);
        }

        #pragma unroll
        for (int ks = 0; ks < 2; ks++) {
            const uint32_t ko = (uint32_t)(ks * 16) * 2;
            uint32_t ah[4][4], al[4][4];
            #pragma unroll
            for (int im = 0; im < 4; im++) {
                const uint32_t ro = (uint32_t)(im * 16 * KSTR) * 2;
                ldmatrix_x4(ah[im], sAh_b + a_off + ro + ko);
                ldmatrix_x4(al[im], sAl_b + a_off + ro + ko);
            }
            uint32_t bh[4][2], bl[4][2];
            #pragma unroll
            for (int p = 0; p < 2; p++) {
                const uint32_t ro = (uint32_t)(p * 16 * KSTR) * 2;
                uint32_t t[4];
                ldmatrix_x4(t, sWh_b + b_off + ro + ko);
                bh[2*p][0] = t[0]; bh[2*p][1] = t[2];
                bh[2*p+1][0] = t[1]; bh[2*p+1][1] = t[3];
                ldmatrix_x4(t, sWl_b + b_off + ro + ko);
                bl[2*p][0] = t[0]; bl[2*p][1] = t[2];
                bl[2*p+1][0] = t[1]; bl[2*p+1][1] = t[3];
            }
            #pragma unroll
            for (int im = 0; im < 4; im++)
                #pragma unroll
                for (int in = 0; in < 4; in++) {
                    mma_bf16(acc[im][in], ah[im], bh[in]);
                    mma_bf16(acc[im][in], ah[im], bl[in]);
                    mma_bf16(acc[im][in], al[im], bh[in]);
                }
        }
        __syncthreads();           // all warps done reading current tile
        if (more) {
            *(uint4*)((char*)sAh + s_off)      = pAh0;
            *(uint4*)((char*)sAh + s_off + 16) = pAh1;
            *(uint4*)((char*)sAl + s_off)      = pAl0;
            *(uint4*)((char*)sAl + s_off + 16) = pAl1;
            *(uint4*)((char*)sWh + s_off)      = pWh0;
            *(uint4*)((char*)sWh + s_off + 16) = pWh1;
            *(uint4*)((char*)sWl + s_off)      = pWl0;
            *(uint4*)((char*)sWl + s_off + 16) = pWl1;
            __syncthreads();       // stores visible before next compute
        }
    }

    const int tr = lane >> 2;
    const int tc = (lane & 3) * 2;
    #pragma unroll
    for (int im = 0; im < 4; im++) {
        #pragma unroll
        for (int in = 0; in < 4; in++) {
            const int m = m0 + wm * 64 + im * 16 + tr;
            const int n = n0 + wn * 32 + in * 8 + tc;
            const float bx = bias[n], by = bias[n + 1];
            float2 v0 = make_float2(acc[im][in][0] + bx, acc[im][in][1] + by);
            float2 v1 = make_float2(acc[im][in][2] + bx, acc[im][in][3] + by);
            *(float2*)(C + (size_t)m * DD + n) = v0;
            *(float2*)(C + (size_t)(m + 8) * DD + n) = v1;
        }
    }
}

// ---------------------------------------------------------------------------
// HMMA flash attention (causal) — unchanged from R9 (verified, 212 us).
// ---------------------------------------------------------------------------
#define QSTR 72

__global__ __launch_bounds__(256) void attn_hmma(
    const float* __restrict__ Qp, const float* __restrict__ Kp,
    const float* __restrict__ Vp, float* __restrict__ Op)
{
    __shared__ __align__(16) __half Ks [64 * QSTR];   // keys  (key-major)
    __shared__ __align__(16) __half VhT[64 * QSTR];   // V hi  (d-major)
    __shared__ __align__(16) __half VlT[64 * QSTR];   // V lo  (d-major)

    const int tid  = threadIdx.x;
    const int warp = tid >> 5;
    const int lane = tid & 31;
    const int g    = lane >> 2;
    const int tg   = lane & 3;

    const int qb = gridDim.x - 1 - blockIdx.x;
    const int bh = blockIdx.y;
    const int b  = bh >> 4;
    const int h  = bh & 15;
    const size_t rowbase = (size_t)b * SS;
    const int col0 = h * DKK;

    const uint32_t Ks_b  = smem_u32(Ks);
    const uint32_t VhT_b = smem_u32(VhT), VlT_b = smem_u32(VlT);

    const int fr  = lane & 15;
    const int fc8 = (lane >> 4) * 8;

    // ---- stage Q (128 x 64) through smem in 2 phases; fragments -> regs ----
    uint32_t qh[4][4], ql[4][4];
    #pragma unroll
    for (int p = 0; p < 2; p++) {
        const int lr = tid >> 2;
        const int db = (tid & 3) * 16;
        const float* src = Qp + (rowbase + (size_t)(qb*128 + p*64 + lr)) * DD + col0 + db;
        __half* dh = Ks  + lr * QSTR + db;
        __half* dl = VhT + lr * QSTR + db;
        #pragma unroll
        for (int i = 0; i < 4; i++) {
            float4 v = *(const float4*)(src + i*4);
            float f0 = v.x * 0.125f, f1 = v.y * 0.125f;
            float f2 = v.z * 0.125f, f3 = v.w * 0.125f;
            __half h0 = __float2half_rn(f0), h1 = __float2half_rn(f1);
            __half h2 = __float2half_rn(f2), h3 = __float2half_rn(f3);
            ((__half2*)(dh + i*4))[0] = __halves2half2(h0, h1);
            ((__half2*)(dh + i*4))[1] = __halves2half2(h2, h3);
            ((__half2*)(dl + i*4))[0] = __halves2half2(
                __float2half_rn(f0 - __half2float(h0)),
                __float2half_rn(f1 - __half2float(h1)));
            ((__half2*)(dl + i*4))[1] = __halves2half2(
                __float2half_rn(f2 - __half2float(h2)),
                __float2half_rn(f3 - __half2float(h3)));
        }
        __syncthreads();
        if ((warp >> 2) == p) {
            const int w2 = warp & 3;
            const uint32_t fo = (uint32_t)((w2*16 + fr) * QSTR + fc8) * 2;
            #pragma unroll
            for (int kc = 0; kc < 4; kc++) {
                ldmatrix_x4(qh[kc], Ks_b  + fo + (uint32_t)(kc*16)*2);
                ldmatrix_x4(ql[kc], VhT_b + fo + (uint32_t)(kc*16)*2);
            }
        }
        __syncthreads();
    }

    float m_run[2] = {-1e30f, -1e30f};
    float l_run[2] = {0.f, 0.f};
    float o[8][4] = {};

    const int kb_max = 2*qb + 1;
    for (int kb = 0; kb <= kb_max; kb++) {
        {
            const int kr = tid >> 2;
            const int db = (tid & 3) * 16;
            const float* ksrc = Kp + (rowbase + (size_t)kb*64 + kr) * DD + col0 + db;
            const float* vsrc = Vp + (rowbase + (size_t)kb*64 + kr) * DD + col0 + db;
            __half* kd = Ks + kr * QSTR + db;
            #pragma unroll
            for (int i = 0; i < 4; i++) {
                float4 v = *(const float4*)(ksrc + i*4);
                ((__half2*)(kd + i*4))[0] = __floats2half2_rn(v.x, v.y);
                ((__half2*)(kd + i*4))[1] = __floats2half2_rn(v.z, v.w);
            }
            #pragma unroll
            for (int i = 0; i < 4; i++) {
                float4 v = *(const float4*)(vsrc + i*4);
                float f[4] = {v.x, v.y, v.z, v.w};
                #pragma unroll
                for (int jj = 0; jj < 4; jj++) {
                    int d = db + i*4 + jj;
                    __half vh = __float2half_rn(f[jj]);
                    __half vl = __float2half_rn(f[jj] - __half2float(vh));
                    VhT[d * QSTR + kr] = vh;
                    VlT[d * QSTR + kr] = vl;
                }
            }
        }
        __syncthreads();

        float s[8][4] = {};
        #pragma unroll
        for (int kc = 0; kc < 4; kc++) {
            #pragma unroll
            for (int g2 = 0; g2 < 4; g2++) {
                uint32_t t[4];
                ldmatrix_x4(t, Ks_b + ((uint32_t)((g2*16 + fr) * QSTR + fc8) + kc*16) * 2);
                mma_f16(s[2*g2],   qh[kc], t[0], t[2]);
                mma_f16(s[2*g2],   ql[kc], t[0], t[2]);
                mma_f16(s[2*g2+1], qh[kc], t[1], t[3]);
                mma_f16(s[2*g2+1], ql[kc], t[1], t[3]);
            }
        }

        const int q0 = qb*128 + warp*16 + g;
        if (kb*64 + 63 > q0) {
            #pragma unroll
            for (int j = 0; j < 8; j++)
                #pragma unroll
                for (int e = 0; e < 4; e++) {
                    int kg = kb*64 + j*8 + tg*2 + (e & 1);
                    int qg = q0 + (e >> 1) * 8;
                    if (kg > qg) s[j][e] = -1e30f;
                }
        }

        float fac[2];
        #pragma unroll
        for (int hf = 0; hf < 2; hf++) {
            float tm = -1e30f;
            #pragma unroll
            for (int j = 0; j < 8; j++)
                tm = fmaxf(tm, fmaxf(s[j][2*hf], s[j][2*hf+1]));
            tm = fmaxf(tm, __shfl_xor_sync(0xffffffffu, tm, 1));
            tm = fmaxf(tm, __shfl_xor_sync(0xffffffffu, tm, 2));
            float mn = fmaxf(m_run[hf], tm);
            fac[hf]  = __expf(m_run[hf] - mn);
            m_run[hf] = mn;
            float rs = 0.f;
            #pragma unroll
            for (int j = 0; j < 8; j++) {
                float p0 = __expf(s[j][2*hf]   - mn);
                float p1 = __expf(s[j][2*hf+1] - mn);
                s[j][2*hf] = p0; s[j][2*hf+1] = p1;
                rs += p0 + p1;
            }
            rs += __shfl_xor_sync(0xffffffffu, rs, 1);
            rs += __shfl_xor_sync(0xffffffffu, rs, 2);
            l_run[hf] = l_run[hf] * fac[hf] + rs;
        }
        #pragma unroll
        for (int j = 0; j < 8; j++) {
            o[j][0] *= fac[0]; o[j][1] *= fac[0];
            o[j][2] *= fac[1]; o[j][3] *= fac[1];
        }

        #pragma unroll
        for (int pk = 0; pk < 4; pk++) {
            uint32_t ap[4];
            __half2 h0 = __floats2half2_rn(s[2*pk][0],   s[2*pk][1]);
            __half2 h1 = __floats2half2_rn(s[2*pk][2],   s[2*pk][3]);
            __half2 h2 = __floats2half2_rn(s[2*pk+1][0], s[2*pk+1][1]);
            __half2 h3 = __floats2half2_rn(s[2*pk+1][2], s[2*pk+1][3]);
            ap[0] = *(uint32_t*)&h0; ap[1] = *(uint32_t*)&h1;
            ap[2] = *(uint32_t*)&h2; ap[3] = *(uint32_t*)&h3;
            const uint32_t vo = ((uint32_t)(fr * QSTR + fc8) + pk*16) * 2;
            #pragma unroll
            for (int g2 = 0; g2 < 4; g2++) {
                uint32_t t[4];
                ldmatrix_x4(t, VhT_b + vo + (uint32_t)(g2*16*QSTR)*2);
                mma_f16(o[2*g2],   ap, t[0], t[2]);
                mma_f16(o[2*g2+1], ap, t[1], t[3]);
                ldmatrix_x4(t, VlT_b + vo + (uint32_t)(g2*16*QSTR)*2);
                mma_f16(o[2*g2],   ap, t[0], t[2]);
                mma_f16(o[2*g2+1], ap, t[1], t[3]);
            }
        }
        __syncthreads();
    }

    const float inv0 = 1.f / l_run[0];
    const float inv1 = 1.f / l_run[1];
    const size_t q0 = rowbase + (size_t)qb*128 + warp*16 + g;
    #pragma unroll
    for (int j = 0; j < 8; j++) {
        const int d = col0 + j*8 + tg*2;
        *(float2*)(Op + q0 * DD + d)       = make_float2(o[j][0]*inv0, o[j][1]*inv0);
        *(float2*)(Op + (q0 + 8) * DD + d) = make_float2(o[j][2]*inv1, o[j][3]*inv1);
    }
}

// ---------------------------------------------------------------------------
// Launch. Inputs (metadata order): q,k,v,mask,wq,bq,wk,bk,wv,bv,wo,bo
// No runtime API in here besides symbol lookups + launches (graph capture).
// ---------------------------------------------------------------------------
extern "C" void kernel_launch(void* const* d_in, const int* in_sizes, int n_in,
                              void* d_out, int out_size)
{
    const float* q  = (const float*)d_in[0];
    const float* k  = (const float*)d_in[1];
    const float* v  = (const float*)d_in[2];
    const float* wq = (const float*)d_in[4];
    const float* bq = (const float*)d_in[5];
    const float* wk = (const float*)d_in[6];
    const float* bk = (const float*)d_in[7];
    const float* wv = (const float*)d_in[8];
    const float* bv = (const float*)d_in[9];
    const float* wo = (const float*)d_in[10];
    const float* bo = (const float*)d_in[11];

    float *Qp, *Kp, *Vp, *Opp;
    __nv_bfloat16 *hi, *lo;
    cudaGetSymbolAddress((void**)&Qp,  g_Q);
    cudaGetSymbolAddress((void**)&Kp,  g_K);
    cudaGetSymbolAddress((void**)&Vp,  g_V);
    cudaGetSymbolAddress((void**)&Opp, g_O);
    cudaGetSymbolAddress((void**)&hi,  g_hi);
    cudaGetSymbolAddress((void**)&lo,  g_lo);

    const int nin4 = (int)(ELEMS_IN / 4);
    const int nw4  = (int)(ELEMS_W / 4);

    split_bf16<<<nin4 / 256, 256>>>(q,  hi + OFF_Q,  lo + OFF_Q,  nin4);
    split_bf16<<<nin4 / 256, 256>>>(k,  hi + OFF_K,  lo + OFF_K,  nin4);
    split_bf16<<<nin4 / 256, 256>>>(v,  hi + OFF_V,  lo + OFF_V,  nin4);
    split_bf16<<<nw4  / 256, 256>>>(wq, hi + OFF_WQ, lo + OFF_WQ, nw4);
    split_bf16<<<nw4  / 256, 256>>>(wk, hi + OFF_WK, lo + OFF_WK, nw4);
    split_bf16<<<nw4  / 256, 256>>>(wv, hi + OFF_WV, lo + OFF_WV, nw4);
    split_bf16<<<nw4  / 256, 256>>>(wo, hi + OFF_WO, lo + OFF_WO, nw4);

    dim3 gemmGrid(DD / 128, MM / 128);   // (8, 32)
    gemm_hmma<<<gemmGrid, 256>>>(hi + OFF_Q, lo + OFF_Q, hi + OFF_WQ, lo + OFF_WQ, bq, Qp);
    gemm_hmma<<<gemmGrid, 256>>>(hi + OFF_K, lo + OFF_K, hi + OFF_WK, lo + OFF_WK, bk, Kp);
    gemm_hmma<<<gemmGrid, 256>>>(hi + OFF_V, lo + OFF_V, hi + OFF_WV, lo + OFF_WV, bv, Vp);

    dim3 attnGrid(SS / 128, BB * HH);    // (16, 32)
    attn_hmma<<<attnGrid, 256>>>(Qp, Kp, Vp, Opp);

    split_bf16<<<nin4 / 256, 256>>>(Opp, hi + OFF_O, lo + OFF_O, nin4);
    gemm_hmma<<<gemmGrid, 256>>>(hi + OFF_O, lo + OFF_O, hi + OFF_WO, lo + OFF_WO, bo, (float*)d_out);
}

// round 12
// speedup vs baseline: 1.4567x; 1.4567x over previous
#include <cuda_runtime.h>
#include <cuda_bf16.h>
#include <cuda_fp16.h>
#include <cstdint>

// Problem constants
#define BB  2
#define SS  2048
#define DD  1024
#define HH  16
#define DKK 64
#define MM  (BB*SS)   // 4096 rows

#define ELEMS_IN ((size_t)MM*DD)   // 4194304
#define ELEMS_W  ((size_t)DD*DD)   // 1048576

// Offsets (elements) inside the shared hi/lo fp16 scratch
#define OFF_Q  ((size_t)0)
#define OFF_K  (ELEMS_IN)
#define OFF_V  (2*ELEMS_IN)
#define OFF_O  (3*ELEMS_IN)
#define OFF_WQ (4*ELEMS_IN)
#define OFF_WK (4*ELEMS_IN + ELEMS_W)
#define OFF_WV (4*ELEMS_IN + 2*ELEMS_W)
#define OFF_WO (4*ELEMS_IN + 3*ELEMS_W)

// Scratch (allocation-free rule: __device__ globals)
__device__ float g_Q[ELEMS_IN];
__device__ float g_K[ELEMS_IN];
__device__ float g_V[ELEMS_IN];
__device__ float g_O[ELEMS_IN];
__device__ __half g_hi[4*ELEMS_IN + 4*ELEMS_W];
__device__ __half g_lo[4*ELEMS_IN];          // lo needed only for A operands

// ---------------------------------------------------------------------------
// helpers
// ---------------------------------------------------------------------------
__device__ __forceinline__ uint32_t smem_u32(const void* p) {
    uint32_t a;
    asm("{ .reg .u64 t; cvta.to.shared.u64 t, %1; cvt.u32.u64 %0, t; }"
        : "=r"(a) : "l"(p));
    return a;
}

__device__ __forceinline__ void ldmatrix_x4(uint32_t* r, uint32_t addr) {
    asm volatile("ldmatrix.sync.aligned.m8n8.x4.shared.b16 {%0,%1,%2,%3}, [%4];"
                 : "=r"(r[0]), "=r"(r[1]), "=r"(r[2]), "=r"(r[3]) : "r"(addr));
}

__device__ __forceinline__ void mma_f16(float* c, const uint32_t* a,
                                        uint32_t b0, uint32_t b1) {
    asm volatile(
        "mma.sync.aligned.m16n8k16.row.col.f32.f16.f16.f32 "
        "{%0,%1,%2,%3}, {%4,%5,%6,%7}, {%8,%9}, {%0,%1,%2,%3};"
        : "+f"(c[0]), "+f"(c[1]), "+f"(c[2]), "+f"(c[3])
        : "r"(a[0]), "r"(a[1]), "r"(a[2]), "r"(a[3]), "r"(b0), "r"(b1));
}

// ---------------------------------------------------------------------------
// fp32 -> (fp16 hi, fp16 lo) split, vectorized x4.  a ~= hi + lo (to 2^-24)
// ---------------------------------------------------------------------------
__global__ __launch_bounds__(256) void split_f16(
    const float* __restrict__ in, __half* __restrict__ hi,
    __half* __restrict__ lo, int n4)
{
    int i = blockIdx.x * blockDim.x + threadIdx.x;
    if (i >= n4) return;
    float4 a = ((const float4*)in)[i];
    __half h0 = __float2half_rn(a.x), h1 = __float2half_rn(a.y);
    __half h2 = __float2half_rn(a.z), h3 = __float2half_rn(a.w);
    __half2 hh0 = __halves2half2(h0, h1);
    __half2 hh1 = __halves2half2(h2, h3);
    __half2 ll0 = __floats2half2_rn(a.x - __half2float(h0), a.y - __half2float(h1));
    __half2 ll1 = __floats2half2_rn(a.z - __half2float(h2), a.w - __half2float(h3));
    uint2 hw, lw;
    hw.x = *(uint32_t*)&hh0; hw.y = *(uint32_t*)&hh1;
    lw.x = *(uint32_t*)&ll0; lw.y = *(uint32_t*)&ll1;
    ((uint2*)hi)[i] = hw;
    ((uint2*)lo)[i] = lw;
}

// fp32 -> fp16 convert (weights), vectorized x4
__global__ __launch_bounds__(256) void cvt_f16(
    const float* __restrict__ in, __half* __restrict__ out, int n4)
{
    int i = blockIdx.x * blockDim.x + threadIdx.x;
    if (i >= n4) return;
    float4 a = ((const float4*)in)[i];
    __half2 h0 = __floats2half2_rn(a.x, a.y);
    __half2 h1 = __floats2half2_rn(a.z, a.w);
    uint2 w;
    w.x = *(uint32_t*)&h0; w.y = *(uint32_t*)&h1;
    ((uint2*)out)[i] = w;
}

// ---------------------------------------------------------------------------
// HMMA fp16x2 GEMM (NT): C[m][n] = sum_k A[m][k]*W[n][k] + bias[n]
// A split fp16 hi/lo; W single fp16 (error = W rounding ~2^-12).
// Block 128x128, BK=32, 256 threads, warp tile 64x32; 2 MMAs per (im,in).
// Structure identical to verified R9 loop (no prefetch — HMMA-issue bound).
// ---------------------------------------------------------------------------
#define KSTR 40

__global__ __launch_bounds__(256) void gemm_hmma(
    const __half* __restrict__ Ahi, const __half* __restrict__ Alo,
    const __half* __restrict__ W, const float* __restrict__ bias,
    float* __restrict__ C)
{
    __shared__ __align__(16) __half sAh[128 * KSTR], sAl[128 * KSTR];
    __shared__ __align__(16) __half sW [128 * KSTR];

    const int tid  = threadIdx.x;
    const int warp = tid >> 5;
    const int lane = tid & 31;
    const int wm   = warp & 1;
    const int wn   = warp >> 1;
    const int m0   = blockIdx.y * 128;
    const int n0   = blockIdx.x * 128;

    const uint32_t sAh_b = smem_u32(sAh), sAl_b = smem_u32(sAl);
    const uint32_t sW_b  = smem_u32(sW);

    float acc[4][4][4] = {};

    const int lrow = tid >> 1;
    const int lcol = (tid & 1) * 16;
    const uint32_t s_off = (uint32_t)(lrow * KSTR + lcol) * 2;

    const int fr = lane & 15;
    const int fc = (lane >> 4) * 8;
    const uint32_t a_off = (uint32_t)((wm * 64 + fr) * KSTR + fc) * 2;
    const uint32_t b_off = (uint32_t)((wn * 32 + fr) * KSTR + fc) * 2;

    for (int k0 = 0; k0 < DD; k0 += 32) {
        const size_t ga = (size_t)(m0 + lrow) * DD + k0 + lcol;
        const size_t gw = (size_t)(n0 + lrow) * DD + k0 + lcol;
        *(uint4*)((char*)sAh + s_off)      = *(const uint4*)(Ahi + ga);
        *(uint4*)((char*)sAh + s_off + 16) = *(const uint4*)(Ahi + ga + 8);
        *(uint4*)((char*)sAl + s_off)      = *(const uint4*)(Alo + ga);
        *(uint4*)((char*)sAl + s_off + 16) = *(const uint4*)(Alo + ga + 8);
        *(uint4*)((char*)sW  + s_off)      = *(const uint4*)(W + gw);
        *(uint4*)((char*)sW  + s_off + 16) = *(const uint4*)(W + gw + 8);
        __syncthreads();

        #pragma unroll
        for (int ks = 0; ks < 2; ks++) {
            const uint32_t ko = (uint32_t)(ks * 16) * 2;
            uint32_t ah[4][4], al[4][4];
            #pragma unroll
            for (int im = 0; im < 4; im++) {
                const uint32_t ro = (uint32_t)(im * 16 * KSTR) * 2;
                ldmatrix_x4(ah[im], sAh_b + a_off + ro + ko);
                ldmatrix_x4(al[im], sAl_b + a_off + ro + ko);
            }
            uint32_t bh[4][2];
            #pragma unroll
            for (int p = 0; p < 2; p++) {
                const uint32_t ro = (uint32_t)(p * 16 * KSTR) * 2;
                uint32_t t[4];
                ldmatrix_x4(t, sW_b + b_off + ro + ko);
                bh[2*p][0] = t[0]; bh[2*p][1] = t[2];
                bh[2*p+1][0] = t[1]; bh[2*p+1][1] = t[3];
            }
            #pragma unroll
            for (int im = 0; im < 4; im++)
                #pragma unroll
                for (int in = 0; in < 4; in++) {
                    mma_f16(acc[im][in], ah[im], bh[in][0], bh[in][1]);
                    mma_f16(acc[im][in], al[im], bh[in][0], bh[in][1]);
                }
        }
        __syncthreads();
    }

    const int tr = lane >> 2;
    const int tc = (lane & 3) * 2;
    #pragma unroll
    for (int im = 0; im < 4; im++) {
        #pragma unroll
        for (int in = 0; in < 4; in++) {
            const int m = m0 + wm * 64 + im * 16 + tr;
            const int n = n0 + wn * 32 + in * 8 + tc;
            const float bx = bias[n], by = bias[n + 1];
            float2 v0 = make_float2(acc[im][in][0] + bx, acc[im][in][1] + by);
            float2 v1 = make_float2(acc[im][in][2] + bx, acc[im][in][3] + by);
            *(float2*)(C + (size_t)m * DD + n) = v0;
            *(float2*)(C + (size_t)(m + 8) * DD + n) = v1;
        }
    }
}

// ---------------------------------------------------------------------------
// HMMA flash attention (causal) — R9 structure, V now SINGLE fp16 (PV MMAs
// halved; error = V rounding ~2^-12, same validated mechanism as K).
// ---------------------------------------------------------------------------
#define QSTR 72

__global__ __launch_bounds__(256) void attn_hmma(
    const float* __restrict__ Qp, const float* __restrict__ Kp,
    const float* __restrict__ Vp, float* __restrict__ Op)
{
    __shared__ __align__(16) __half Ks [64 * QSTR];   // keys  (key-major)
    __shared__ __align__(16) __half VT [64 * QSTR];   // V     (d-major)

    const int tid  = threadIdx.x;
    const int warp = tid >> 5;
    const int lane = tid & 31;
    const int g    = lane >> 2;
    const int tg   = lane & 3;

    const int qb = gridDim.x - 1 - blockIdx.x;
    const int bh = blockIdx.y;
    const int b  = bh >> 4;
    const int h  = bh & 15;
    const size_t rowbase = (size_t)b * SS;
    const int col0 = h * DKK;

    const uint32_t Ks_b = smem_u32(Ks);
    const uint32_t VT_b = smem_u32(VT);

    const int fr  = lane & 15;
    const int fc8 = (lane >> 4) * 8;

    // ---- stage Q (128 x 64) through smem in 2 phases; fragments -> regs ----
    uint32_t qh[4][4], ql[4][4];
    #pragma unroll
    for (int p = 0; p < 2; p++) {
        const int lr = tid >> 2;
        const int db = (tid & 3) * 16;
        const float* src = Qp + (rowbase + (size_t)(qb*128 + p*64 + lr)) * DD + col0 + db;
        __half* dh = Ks + lr * QSTR + db;
        __half* dl = VT + lr * QSTR + db;
        #pragma unroll
        for (int i = 0; i < 4; i++) {
            float4 v = *(const float4*)(src + i*4);
            float f0 = v.x * 0.125f, f1 = v.y * 0.125f;
            float f2 = v.z * 0.125f, f3 = v.w * 0.125f;
            __half h0 = __float2half_rn(f0), h1 = __float2half_rn(f1);
            __half h2 = __float2half_rn(f2), h3 = __float2half_rn(f3);
            ((__half2*)(dh + i*4))[0] = __halves2half2(h0, h1);
            ((__half2*)(dh + i*4))[1] = __halves2half2(h2, h3);
            ((__half2*)(dl + i*4))[0] = __halves2half2(
                __float2half_rn(f0 - __half2float(h0)),
                __float2half_rn(f1 - __half2float(h1)));
            ((__half2*)(dl + i*4))[1] = __halves2half2(
                __float2half_rn(f2 - __half2float(h2)),
                __float2half_rn(f3 - __half2float(h3)));
        }
        __syncthreads();
        if ((warp >> 2) == p) {
            const int w2 = warp & 3;
            const uint32_t fo = (uint32_t)((w2*16 + fr) * QSTR + fc8) * 2;
            #pragma unroll
            for (int kc = 0; kc < 4; kc++) {
                ldmatrix_x4(qh[kc], Ks_b + fo + (uint32_t)(kc*16)*2);
                ldmatrix_x4(ql[kc], VT_b + fo + (uint32_t)(kc*16)*2);
            }
        }
        __syncthreads();
    }

    float m_run[2] = {-1e30f, -1e30f};
    float l_run[2] = {0.f, 0.f};
    float o[8][4] = {};

    const int kb_max = 2*qb + 1;
    for (int kb = 0; kb <= kb_max; kb++) {
        // ---- load K tile (key-major fp16) + V tile (transposed fp16) ----
        {
            const int kr = tid >> 2;
            const int db = (tid & 3) * 16;
            const float* ksrc = Kp + (rowbase + (size_t)kb*64 + kr) * DD + col0 + db;
            const float* vsrc = Vp + (rowbase + (size_t)kb*64 + kr) * DD + col0 + db;
            __half* kd = Ks + kr * QSTR + db;
            #pragma unroll
            for (int i = 0; i < 4; i++) {
                float4 v = *(const float4*)(ksrc + i*4);
                ((__half2*)(kd + i*4))[0] = __floats2half2_rn(v.x, v.y);
                ((__half2*)(kd + i*4))[1] = __floats2half2_rn(v.z, v.w);
            }
            #pragma unroll
            for (int i = 0; i < 4; i++) {
                float4 v = *(const float4*)(vsrc + i*4);
                float f[4] = {v.x, v.y, v.z, v.w};
                #pragma unroll
                for (int jj = 0; jj < 4; jj++) {
                    int d = db + i*4 + jj;
                    VT[d * QSTR + kr] = __float2half_rn(f[jj]);
                }
            }
        }
        __syncthreads();

        // ---- S = Q K^T (scaled) ----
        float s[8][4] = {};
        #pragma unroll
        for (int kc = 0; kc < 4; kc++) {
            #pragma unroll
            for (int g2 = 0; g2 < 4; g2++) {
                uint32_t t[4];
                ldmatrix_x4(t, Ks_b + ((uint32_t)((g2*16 + fr) * QSTR + fc8) + kc*16) * 2);
                mma_f16(s[2*g2],   qh[kc], t[0], t[2]);
                mma_f16(s[2*g2],   ql[kc], t[0], t[2]);
                mma_f16(s[2*g2+1], qh[kc], t[1], t[3]);
                mma_f16(s[2*g2+1], ql[kc], t[1], t[3]);
            }
        }

        // ---- causal mask ----
        const int q0 = qb*128 + warp*16 + g;
        if (kb*64 + 63 > q0) {
            #pragma unroll
            for (int j = 0; j < 8; j++)
                #pragma unroll
                for (int e = 0; e < 4; e++) {
                    int kg = kb*64 + j*8 + tg*2 + (e & 1);
                    int qg = q0 + (e >> 1) * 8;
                    if (kg > qg) s[j][e] = -1e30f;
                }
        }

        // ---- online softmax ----
        float fac[2];
        #pragma unroll
        for (int hf = 0; hf < 2; hf++) {
            float tm = -1e30f;
            #pragma unroll
            for (int j = 0; j < 8; j++)
                tm = fmaxf(tm, fmaxf(s[j][2*hf], s[j][2*hf+1]));
            tm = fmaxf(tm, __shfl_xor_sync(0xffffffffu, tm, 1));
            tm = fmaxf(tm, __shfl_xor_sync(0xffffffffu, tm, 2));
            float mn = fmaxf(m_run[hf], tm);
            fac[hf]  = __expf(m_run[hf] - mn);
            m_run[hf] = mn;
            float rs = 0.f;
            #pragma unroll
            for (int j = 0; j < 8; j++) {
                float p0 = __expf(s[j][2*hf]   - mn);
                float p1 = __expf(s[j][2*hf+1] - mn);
                s[j][2*hf] = p0; s[j][2*hf+1] = p1;
                rs += p0 + p1;
            }
            rs += __shfl_xor_sync(0xffffffffu, rs, 1);
            rs += __shfl_xor_sync(0xffffffffu, rs, 2);
            l_run[hf] = l_run[hf] * fac[hf] + rs;
        }
        #pragma unroll
        for (int j = 0; j < 8; j++) {
            o[j][0] *= fac[0]; o[j][1] *= fac[0];
            o[j][2] *= fac[1]; o[j][3] *= fac[1];
        }

        // ---- O += P V  (P fp16 from S fragments; V single) ----
        #pragma unroll
        for (int pk = 0; pk < 4; pk++) {
            uint32_t ap[4];
            __half2 h0 = __floats2half2_rn(s[2*pk][0],   s[2*pk][1]);
            __half2 h1 = __floats2half2_rn(s[2*pk][2],   s[2*pk][3]);
            __half2 h2 = __floats2half2_rn(s[2*pk+1][0], s[2*pk+1][1]);
            __half2 h3 = __floats2half2_rn(s[2*pk+1][2], s[2*pk+1][3]);
            ap[0] = *(uint32_t*)&h0; ap[1] = *(uint32_t*)&h1;
            ap[2] = *(uint32_t*)&h2; ap[3] = *(uint32_t*)&h3;
            const uint32_t vo = ((uint32_t)(fr * QSTR + fc8) + pk*16) * 2;
            #pragma unroll
            for (int g2 = 0; g2 < 4; g2++) {
                uint32_t t[4];
                ldmatrix_x4(t, VT_b + vo + (uint32_t)(g2*16*QSTR)*2);
                mma_f16(o[2*g2],   ap, t[0], t[2]);
                mma_f16(o[2*g2+1], ap, t[1], t[3]);
            }
        }
        __syncthreads();
    }

    const float inv0 = 1.f / l_run[0];
    const float inv1 = 1.f / l_run[1];
    const size_t q0 = rowbase + (size_t)qb*128 + warp*16 + g;
    #pragma unroll
    for (int j = 0; j < 8; j++) {
        const int d = col0 + j*8 + tg*2;
        *(float2*)(Op + q0 * DD + d)       = make_float2(o[j][0]*inv0, o[j][1]*inv0);
        *(float2*)(Op + (q0 + 8) * DD + d) = make_float2(o[j][2]*inv1, o[j][3]*inv1);
    }
}

// ---------------------------------------------------------------------------
// Launch. Inputs (metadata order): q,k,v,mask,wq,bq,wk,bk,wv,bv,wo,bo
// No runtime API in here besides symbol lookups + launches (graph capture).
// ---------------------------------------------------------------------------
extern "C" void kernel_launch(void* const* d_in, const int* in_sizes, int n_in,
                              void* d_out, int out_size)
{
    const float* q  = (const float*)d_in[0];
    const float* k  = (const float*)d_in[1];
    const float* v  = (const float*)d_in[2];
    const float* wq = (const float*)d_in[4];
    const float* bq = (const float*)d_in[5];
    const float* wk = (const float*)d_in[6];
    const float* bk = (const float*)d_in[7];
    const float* wv = (const float*)d_in[8];
    const float* bv = (const float*)d_in[9];
    const float* wo = (const float*)d_in[10];
    const float* bo = (const float*)d_in[11];

    float *Qp, *Kp, *Vp, *Opp;
    __half *hi, *lo;
    cudaGetSymbolAddress((void**)&Qp,  g_Q);
    cudaGetSymbolAddress((void**)&Kp,  g_K);
    cudaGetSymbolAddress((void**)&Vp,  g_V);
    cudaGetSymbolAddress((void**)&Opp, g_O);
    cudaGetSymbolAddress((void**)&hi,  g_hi);
    cudaGetSymbolAddress((void**)&lo,  g_lo);

    const int nin4 = (int)(ELEMS_IN / 4);
    const int nw4  = (int)(ELEMS_W / 4);

    // A operands: fp16 hi/lo split; weights: single fp16
    split_f16<<<nin4 / 256, 256>>>(q,  hi + OFF_Q,  lo + OFF_Q,  nin4);
    split_f16<<<nin4 / 256, 256>>>(k,  hi + OFF_K,  lo + OFF_K,  nin4);
    split_f16<<<nin4 / 256, 256>>>(v,  hi + OFF_V,  lo + OFF_V,  nin4);
    cvt_f16<<<nw4 / 256, 256>>>(wq, hi + OFF_WQ, nw4);
    cvt_f16<<<nw4 / 256, 256>>>(wk, hi + OFF_WK, nw4);
    cvt_f16<<<nw4 / 256, 256>>>(wv, hi + OFF_WV, nw4);
    cvt_f16<<<nw4 / 256, 256>>>(wo, hi + OFF_WO, nw4);

    dim3 gemmGrid(DD / 128, MM / 128);   // (8, 32)
    gemm_hmma<<<gemmGrid, 256>>>(hi + OFF_Q, lo + OFF_Q, hi + OFF_WQ, bq, Qp);
    gemm_hmma<<<gemmGrid, 256>>>(hi + OFF_K, lo + OFF_K, hi + OFF_WK, bk, Kp);
    gemm_hmma<<<gemmGrid, 256>>>(hi + OFF_V, lo + OFF_V, hi + OFF_WV, bv, Vp);

    dim3 attnGrid(SS / 128, BB * HH);    // (16, 32)
    attn_hmma<<<attnGrid, 256>>>(Qp, Kp, Vp, Opp);

    split_f16<<<nin4 / 256, 256>>>(Opp, hi + OFF_O, lo + OFF_O, nin4);
    gemm_hmma<<<gemmGrid, 256>>>(hi + OFF_O, lo + OFF_O, hi + OFF_WO, bo, (float*)d_out);
}

// round 13
// speedup vs baseline: 1.8781x; 1.2893x over previous
#include <cuda_runtime.h>
#include <cuda_fp16.h>
#include <cstdint>

// Problem constants
#define BB  2
#define SS  2048
#define DD  1024
#define HH  16
#define DKK 64
#define MM  (BB*SS)   // 4096 rows

#define ELEMS_IN ((size_t)MM*DD)   // 4194304
#define ELEMS_W  ((size_t)DD*DD)   // 1048576

// Offsets (elements) inside the fp16 scratch
#define OFF_Q  ((size_t)0)
#define OFF_K  (ELEMS_IN)
#define OFF_V  (2*ELEMS_IN)
#define OFF_O  (3*ELEMS_IN)
#define OFF_WQ (4*ELEMS_IN)
#define OFF_WK (4*ELEMS_IN + ELEMS_W)
#define OFF_WV (4*ELEMS_IN + 2*ELEMS_W)
#define OFF_WO (4*ELEMS_IN + 3*ELEMS_W)

// Scratch (allocation-free rule: __device__ globals)
__device__ float g_Q[ELEMS_IN];
__device__ float g_K[ELEMS_IN];
__device__ float g_V[ELEMS_IN];
__device__ float g_O[ELEMS_IN];
__device__ __half g_h16[4*ELEMS_IN + 4*ELEMS_W];

// ---------------------------------------------------------------------------
// helpers
// ---------------------------------------------------------------------------
__device__ __forceinline__ uint32_t smem_u32(const void* p) {
    uint32_t a;
    asm("{ .reg .u64 t; cvta.to.shared.u64 t, %1; cvt.u32.u64 %0, t; }"
        : "=r"(a) : "l"(p));
    return a;
}

__device__ __forceinline__ void ldmatrix_x4(uint32_t* r, uint32_t addr) {
    asm volatile("ldmatrix.sync.aligned.m8n8.x4.shared.b16 {%0,%1,%2,%3}, [%4];"
                 : "=r"(r[0]), "=r"(r[1]), "=r"(r[2]), "=r"(r[3]) : "r"(addr));
}

__device__ __forceinline__ void mma_f16(float* c, const uint32_t* a,
                                        uint32_t b0, uint32_t b1) {
    asm volatile(
        "mma.sync.aligned.m16n8k16.row.col.f32.f16.f16.f32 "
        "{%0,%1,%2,%3}, {%4,%5,%6,%7}, {%8,%9}, {%0,%1,%2,%3};"
        : "+f"(c[0]), "+f"(c[1]), "+f"(c[2]), "+f"(c[3])
        : "r"(a[0]), "r"(a[1]), "r"(a[2]), "r"(a[3]), "r"(b0), "r"(b1));
}

// fp32 -> fp16 convert, vectorized x4
__global__ __launch_bounds__(256) void cvt_f16(
    const float* __restrict__ in, __half* __restrict__ out, int n4)
{
    int i = blockIdx.x * blockDim.x + threadIdx.x;
    if (i >= n4) return;
    float4 a = ((const float4*)in)[i];
    __half2 h0 = __floats2half2_rn(a.x, a.y);
    __half2 h1 = __floats2half2_rn(a.z, a.w);
    uint2 w;
    w.x = *(uint32_t*)&h0; w.y = *(uint32_t*)&h1;
    ((uint2*)out)[i] = w;
}

// ---------------------------------------------------------------------------
// HMMA fp16 GEMM (NT): C[m][n] = sum_k A[m][k]*W[n][k] + bias[n]
// A and W single fp16 (error ~ combined rounding, counted in global budget).
// Block 128x128, BK=32, 256 threads, warp tile 64x32; 1 MMA per (im,in)/ks.
// 2 smem arrays (20 KB) -> 2 CTAs/SM cover each other's syncs.
// ---------------------------------------------------------------------------
#define KSTR 40

__global__ __launch_bounds__(256) void gemm_hmma(
    const __half* __restrict__ A, const __half* __restrict__ W,
    const float* __restrict__ bias, float* __restrict__ C)
{
    __shared__ __align__(16) __half sA[128 * KSTR];
    __shared__ __align__(16) __half sW[128 * KSTR];

    const int tid  = threadIdx.x;
    const int warp = tid >> 5;
    const int lane = tid & 31;
    const int wm   = warp & 1;
    const int wn   = warp >> 1;
    const int m0   = blockIdx.y * 128;
    const int n0   = blockIdx.x * 128;

    const uint32_t sA_b = smem_u32(sA);
    const uint32_t sW_b = smem_u32(sW);

    float acc[4][4][4] = {};

    const int lrow = tid >> 1;
    const int lcol = (tid & 1) * 16;
    const uint32_t s_off = (uint32_t)(lrow * KSTR + lcol) * 2;

    const int fr = lane & 15;
    const int fc = (lane >> 4) * 8;
    const uint32_t a_off = (uint32_t)((wm * 64 + fr) * KSTR + fc) * 2;
    const uint32_t b_off = (uint32_t)((wn * 32 + fr) * KSTR + fc) * 2;

    for (int k0 = 0; k0 < DD; k0 += 32) {
        const size_t ga = (size_t)(m0 + lrow) * DD + k0 + lcol;
        const size_t gw = (size_t)(n0 + lrow) * DD + k0 + lcol;
        *(uint4*)((char*)sA + s_off)      = *(const uint4*)(A + ga);
        *(uint4*)((char*)sA + s_off + 16) = *(const uint4*)(A + ga + 8);
        *(uint4*)((char*)sW + s_off)      = *(const uint4*)(W + gw);
        *(uint4*)((char*)sW + s_off + 16) = *(const uint4*)(W + gw + 8);
        __syncthreads();

        #pragma unroll
        for (int ks = 0; ks < 2; ks++) {
            const uint32_t ko = (uint32_t)(ks * 16) * 2;
            uint32_t ah[4][4];
            #pragma unroll
            for (int im = 0; im < 4; im++) {
                const uint32_t ro = (uint32_t)(im * 16 * KSTR) * 2;
                ldmatrix_x4(ah[im], sA_b + a_off + ro + ko);
            }
            uint32_t bh[4][2];
            #pragma unroll
            for (int p = 0; p < 2; p++) {
                const uint32_t ro = (uint32_t)(p * 16 * KSTR) * 2;
                uint32_t t[4];
                ldmatrix_x4(t, sW_b + b_off + ro + ko);
                bh[2*p][0] = t[0]; bh[2*p][1] = t[2];
                bh[2*p+1][0] = t[1]; bh[2*p+1][1] = t[3];
            }
            #pragma unroll
            for (int im = 0; im < 4; im++)
                #pragma unroll
                for (int in = 0; in < 4; in++)
                    mma_f16(acc[im][in], ah[im], bh[in][0], bh[in][1]);
        }
        __syncthreads();
    }

    const int tr = lane >> 2;
    const int tc = (lane & 3) * 2;
    #pragma unroll
    for (int im = 0; im < 4; im++) {
        #pragma unroll
        for (int in = 0; in < 4; in++) {
            const int m = m0 + wm * 64 + im * 16 + tr;
            const int n = n0 + wn * 32 + in * 8 + tc;
            const float bx = bias[n], by = bias[n + 1];
            float2 v0 = make_float2(acc[im][in][0] + bx, acc[im][in][1] + by);
            float2 v1 = make_float2(acc[im][in][2] + bx, acc[im][in][3] + by);
            *(float2*)(C + (size_t)m * DD + n) = v0;
            *(float2*)(C + (size_t)(m + 8) * DD + n) = v1;
        }
    }
}

// ---------------------------------------------------------------------------
// HMMA flash attention (causal) — unchanged from R12 (verified).
// Q split fp16 hi/lo (scale folded); K, V, P single fp16.
// ---------------------------------------------------------------------------
#define QSTR 72

__global__ __launch_bounds__(256) void attn_hmma(
    const float* __restrict__ Qp, const float* __restrict__ Kp,
    const float* __restrict__ Vp, float* __restrict__ Op)
{
    __shared__ __align__(16) __half Ks [64 * QSTR];   // keys  (key-major)
    __shared__ __align__(16) __half VT [64 * QSTR];   // V     (d-major)

    const int tid  = threadIdx.x;
    const int warp = tid >> 5;
    const int lane = tid & 31;
    const int g    = lane >> 2;
    const int tg   = lane & 3;

    const int qb = gridDim.x - 1 - blockIdx.x;
    const int bh = blockIdx.y;
    const int b  = bh >> 4;
    const int h  = bh & 15;
    const size_t rowbase = (size_t)b * SS;
    const int col0 = h * DKK;

    const uint32_t Ks_b = smem_u32(Ks);
    const uint32_t VT_b = smem_u32(VT);

    const int fr  = lane & 15;
    const int fc8 = (lane >> 4) * 8;

    // ---- stage Q (128 x 64) through smem in 2 phases; fragments -> regs ----
    uint32_t qh[4][4], ql[4][4];
    #pragma unroll
    for (int p = 0; p < 2; p++) {
        const int lr = tid >> 2;
        const int db = (tid & 3) * 16;
        const float* src = Qp + (rowbase + (size_t)(qb*128 + p*64 + lr)) * DD + col0 + db;
        __half* dh = Ks + lr * QSTR + db;
        __half* dl = VT + lr * QSTR + db;
        #pragma unroll
        for (int i = 0; i < 4; i++) {
            float4 v = *(const float4*)(src + i*4);
            float f0 = v.x * 0.125f, f1 = v.y * 0.125f;
            float f2 = v.z * 0.125f, f3 = v.w * 0.125f;
            __half h0 = __float2half_rn(f0), h1 = __float2half_rn(f1);
            __half h2 = __float2half_rn(f2), h3 = __float2half_rn(f3);
            ((__half2*)(dh + i*4))[0] = __halves2half2(h0, h1);
            ((__half2*)(dh + i*4))[1] = __halves2half2(h2, h3);
            ((__half2*)(dl + i*4))[0] = __halves2half2(
                __float2half_rn(f0 - __half2float(h0)),
                __float2half_rn(f1 - __half2float(h1)));
            ((__half2*)(dl + i*4))[1] = __halves2half2(
                __float2half_rn(f2 - __half2float(h2)),
                __float2half_rn(f3 - __half2float(h3)));
        }
        __syncthreads();
        if ((warp >> 2) == p) {
            const int w2 = warp & 3;
            const uint32_t fo = (uint32_t)((w2*16 + fr) * QSTR + fc8) * 2;
            #pragma unroll
            for (int kc = 0; kc < 4; kc++) {
                ldmatrix_x4(qh[kc], Ks_b + fo + (uint32_t)(kc*16)*2);
                ldmatrix_x4(ql[kc], VT_b + fo + (uint32_t)(kc*16)*2);
            }
        }
        __syncthreads();
    }

    float m_run[2] = {-1e30f, -1e30f};
    float l_run[2] = {0.f, 0.f};
    float o[8][4] = {};

    const int kb_max = 2*qb + 1;
    for (int kb = 0; kb <= kb_max; kb++) {
        // ---- load K tile (key-major fp16) + V tile (transposed fp16) ----
        {
            const int kr = tid >> 2;
            const int db = (tid & 3) * 16;
            const float* ksrc = Kp + (rowbase + (size_t)kb*64 + kr) * DD + col0 + db;
            const float* vsrc = Vp + (rowbase + (size_t)kb*64 + kr) * DD + col0 + db;
            __half* kd = Ks + kr * QSTR + db;
            #pragma unroll
            for (int i = 0; i < 4; i++) {
                float4 v = *(const float4*)(ksrc + i*4);
                ((__half2*)(kd + i*4))[0] = __floats2half2_rn(v.x, v.y);
                ((__half2*)(kd + i*4))[1] = __floats2half2_rn(v.z, v.w);
            }
            #pragma unroll
            for (int i = 0; i < 4; i++) {
                float4 v = *(const float4*)(vsrc + i*4);
                float f[4] = {v.x, v.y, v.z, v.w};
                #pragma unroll
                for (int jj = 0; jj < 4; jj++) {
                    int d = db + i*4 + jj;
                    VT[d * QSTR + kr] = __float2half_rn(f[jj]);
                }
            }
        }
        __syncthreads();

        // ---- S = Q K^T (scaled) ----
        float s[8][4] = {};
        #pragma unroll
        for (int kc = 0; kc < 4; kc++) {
            #pragma unroll
            for (int g2 = 0; g2 < 4; g2++) {
                uint32_t t[4];
                ldmatrix_x4(t, Ks_b + ((uint32_t)((g2*16 + fr) * QSTR + fc8) + kc*16) * 2);
                mma_f16(s[2*g2],   qh[kc], t[0], t[2]);
                mma_f16(s[2*g2],   ql[kc], t[0], t[2]);
                mma_f16(s[2*g2+1], qh[kc], t[1], t[3]);
                mma_f16(s[2*g2+1], ql[kc], t[1], t[3]);
            }
        }

        // ---- causal mask ----
        const int q0 = qb*128 + warp*16 + g;
        if (kb*64 + 63 > q0) {
            #pragma unroll
            for (int j = 0; j < 8; j++)
                #pragma unroll
                for (int e = 0; e < 4; e++) {
                    int kg = kb*64 + j*8 + tg*2 + (e & 1);
                    int qg = q0 + (e >> 1) * 8;
                    if (kg > qg) s[j][e] = -1e30f;
                }
        }

        // ---- online softmax ----
        float fac[2];
        #pragma unroll
        for (int hf = 0; hf < 2; hf++) {
            float tm = -1e30f;
            #pragma unroll
            for (int j = 0; j < 8; j++)
                tm = fmaxf(tm, fmaxf(s[j][2*hf], s[j][2*hf+1]));
            tm = fmaxf(tm, __shfl_xor_sync(0xffffffffu, tm, 1));
            tm = fmaxf(tm, __shfl_xor_sync(0xffffffffu, tm, 2));
            float mn = fmaxf(m_run[hf], tm);
            fac[hf]  = __expf(m_run[hf] - mn);
            m_run[hf] = mn;
            float rs = 0.f;
            #pragma unroll
            for (int j = 0; j < 8; j++) {
                float p0 = __expf(s[j][2*hf]   - mn);
                float p1 = __expf(s[j][2*hf+1] - mn);
                s[j][2*hf] = p0; s[j][2*hf+1] = p1;
                rs += p0 + p1;
            }
            rs += __shfl_xor_sync(0xffffffffu, rs, 1);
            rs += __shfl_xor_sync(0xffffffffu, rs, 2);
            l_run[hf] = l_run[hf] * fac[hf] + rs;
        }
        #pragma unroll
        for (int j = 0; j < 8; j++) {
            o[j][0] *= fac[0]; o[j][1] *= fac[0];
            o[j][2] *= fac[1]; o[j][3] *= fac[1];
        }

        // ---- O += P V ----
        #pragma unroll
        for (int pk = 0; pk < 4; pk++) {
            uint32_t ap[4];
            __half2 h0 = __floats2half2_rn(s[2*pk][0],   s[2*pk][1]);
            __half2 h1 = __floats2half2_rn(s[2*pk][2],   s[2*pk][3]);
            __half2 h2 = __floats2half2_rn(s[2*pk+1][0], s[2*pk+1][1]);
            __half2 h3 = __floats2half2_rn(s[2*pk+1][2], s[2*pk+1][3]);
            ap[0] = *(uint32_t*)&h0; ap[1] = *(uint32_t*)&h1;
            ap[2] = *(uint32_t*)&h2; ap[3] = *(uint32_t*)&h3;
            const uint32_t vo = ((uint32_t)(fr * QSTR + fc8) + pk*16) * 2;
            #pragma unroll
            for (int g2 = 0; g2 < 4; g2++) {
                uint32_t t[4];
                ldmatrix_x4(t, VT_b + vo + (uint32_t)(g2*16*QSTR)*2);
                mma_f16(o[2*g2],   ap, t[0], t[2]);
                mma_f16(o[2*g2+1], ap, t[1], t[3]);
            }
        }
        __syncthreads();
    }

    const float inv0 = 1.f / l_run[0];
    const float inv1 = 1.f / l_run[1];
    const size_t q0 = rowbase + (size_t)qb*128 + warp*16 + g;
    #pragma unroll
    for (int j = 0; j < 8; j++) {
        const int d = col0 + j*8 + tg*2;
        *(float2*)(Op + q0 * DD + d)       = make_float2(o[j][0]*inv0, o[j][1]*inv0);
        *(float2*)(Op + (q0 + 8) * DD + d) = make_float2(o[j][2]*inv1, o[j][3]*inv1);
    }
}

// ---------------------------------------------------------------------------
// Launch. Inputs (metadata order): q,k,v,mask,wq,bq,wk,bk,wv,bv,wo,bo
// No runtime API in here besides symbol lookups + launches (graph capture).
// ---------------------------------------------------------------------------
extern "C" void kernel_launch(void* const* d_in, const int* in_sizes, int n_in,
                              void* d_out, int out_size)
{
    const float* q  = (const float*)d_in[0];
    const float* k  = (const float*)d_in[1];
    const float* v  = (const float*)d_in[2];
    const float* wq = (const float*)d_in[4];
    const float* bq = (const float*)d_in[5];
    const float* wk = (const float*)d_in[6];
    const float* bk = (const float*)d_in[7];
    const float* wv = (const float*)d_in[8];
    const float* bv = (const float*)d_in[9];
    const float* wo = (const float*)d_in[10];
    const float* bo = (const float*)d_in[11];

    float *Qp, *Kp, *Vp, *Opp;
    __half *h16;
    cudaGetSymbolAddress((void**)&Qp,  g_Q);
    cudaGetSymbolAddress((void**)&Kp,  g_K);
    cudaGetSymbolAddress((void**)&Vp,  g_V);
    cudaGetSymbolAddress((void**)&Opp, g_O);
    cudaGetSymbolAddress((void**)&h16, g_h16);

    const int nin4 = (int)(ELEMS_IN / 4);
    const int nw4  = (int)(ELEMS_W / 4);

    cvt_f16<<<nin4 / 256, 256>>>(q,  h16 + OFF_Q,  nin4);
    cvt_f16<<<nin4 / 256, 256>>>(k,  h16 + OFF_K,  nin4);
    cvt_f16<<<nin4 / 256, 256>>>(v,  h16 + OFF_V,  nin4);
    cvt_f16<<<nw4 / 256, 256>>>(wq, h16 + OFF_WQ, nw4);
    cvt_f16<<<nw4 / 256, 256>>>(wk, h16 + OFF_WK, nw4);
    cvt_f16<<<nw4 / 256, 256>>>(wv, h16 + OFF_WV, nw4);
    cvt_f16<<<nw4 / 256, 256>>>(wo, h16 + OFF_WO, nw4);

    dim3 gemmGrid(DD / 128, MM / 128);   // (8, 32)
    gemm_hmma<<<gemmGrid, 256>>>(h16 + OFF_Q, h16 + OFF_WQ, bq, Qp);
    gemm_hmma<<<gemmGrid, 256>>>(h16 + OFF_K, h16 + OFF_WK, bk, Kp);
    gemm_hmma<<<gemmGrid, 256>>>(h16 + OFF_V, h16 + OFF_WV, bv, Vp);

    dim3 attnGrid(SS / 128, BB * HH);    // (16, 32)
    attn_hmma<<<attnGrid, 256>>>(Qp, Kp, Vp, Opp);

    cvt_f16<<<nin4 / 256, 256>>>(Opp, h16 + OFF_O, nin4);
    gemm_hmma<<<gemmGrid, 256>>>(h16 + OFF_O, h16 + OFF_WO, bo, (float*)d_out);
}

// round 15
// speedup vs baseline: 2.2412x; 1.1933x over previous
#include <cuda_runtime.h>
#include <cuda_fp16.h>
#include <cstdint>

// Problem constants
#define BB  2
#define SS  2048
#define DD  1024
#define HH  16
#define DKK 64
#define MM  (BB*SS)   // 4096 rows

#define ELEMS_IN ((size_t)MM*DD)   // 4194304
#define ELEMS_W  ((size_t)DD*DD)   // 1048576

// g_in16: converted inputs + weights
#define OFF_IQ ((size_t)0)
#define OFF_IK (ELEMS_IN)
#define OFF_IV (2*ELEMS_IN)
#define OFF_WQ (3*ELEMS_IN)
#define OFF_WK (3*ELEMS_IN + ELEMS_W)
#define OFF_WV (3*ELEMS_IN + 2*ELEMS_W)
#define OFF_WO (3*ELEMS_IN + 3*ELEMS_W)
// g_p16: projected Q/K/V + attention output O (all fp16)
#define OFF_PQ ((size_t)0)
#define OFF_PK (ELEMS_IN)
#define OFF_PV (2*ELEMS_IN)
#define OFF_PO (3*ELEMS_IN)

// Scratch (allocation-free rule: __device__ globals)
__device__ __half g_in16[3*ELEMS_IN + 4*ELEMS_W];
__device__ __half g_p16 [4*ELEMS_IN];

// ---------------------------------------------------------------------------
// helpers
// ---------------------------------------------------------------------------
__device__ __forceinline__ uint32_t smem_u32(const void* p) {
    uint32_t a;
    asm("{ .reg .u64 t; cvta.to.shared.u64 t, %1; cvt.u32.u64 %0, t; }"
        : "=r"(a) : "l"(p));
    return a;
}

__device__ __forceinline__ void ldmatrix_x4(uint32_t* r, uint32_t addr) {
    asm volatile("ldmatrix.sync.aligned.m8n8.x4.shared.b16 {%0,%1,%2,%3}, [%4];"
                 : "=r"(r[0]), "=r"(r[1]), "=r"(r[2]), "=r"(r[3]) : "r"(addr));
}

__device__ __forceinline__ void ldmatrix_x4_trans(uint32_t* r, uint32_t addr) {
    asm volatile("ldmatrix.sync.aligned.m8n8.x4.trans.shared.b16 {%0,%1,%2,%3}, [%4];"
                 : "=r"(r[0]), "=r"(r[1]), "=r"(r[2]), "=r"(r[3]) : "r"(addr));
}

__device__ __forceinline__ void mma_f16(float* c, const uint32_t* a,
                                        uint32_t b0, uint32_t b1) {
    asm volatile(
        "mma.sync.aligned.m16n8k16.row.col.f32.f16.f16.f32 "
        "{%0,%1,%2,%3}, {%4,%5,%6,%7}, {%8,%9}, {%0,%1,%2,%3};"
        : "+f"(c[0]), "+f"(c[1]), "+f"(c[2]), "+f"(c[3])
        : "r"(a[0]), "r"(a[1]), "r"(a[2]), "r"(a[3]), "r"(b0), "r"(b1));
}

// fp32 -> fp16 convert, vectorized x4
__global__ __launch_bounds__(256) void cvt_f16(
    const float* __restrict__ in, __half* __restrict__ out, int n4)
{
    int i = blockIdx.x * blockDim.x + threadIdx.x;
    if (i >= n4) return;
    float4 a = ((const float4*)in)[i];
    __half2 h0 = __floats2half2_rn(a.x, a.y);
    __half2 h1 = __floats2half2_rn(a.z, a.w);
    uint2 w;
    w.x = *(uint32_t*)&h0; w.y = *(uint32_t*)&h1;
    ((uint2*)out)[i] = w;
}

// ---------------------------------------------------------------------------
// HMMA fp16 GEMM (NT): C[m][n] = sum_k A[m][k]*W[n][k] + bias[n]
// Structure verified in R13 (78% of HMMA issue ceiling). Templated output:
// fp16 for the 3 projections (attention input), fp32 for the final output.
// ---------------------------------------------------------------------------
#define KSTR 40

template <bool HALF_OUT>
__global__ __launch_bounds__(256) void gemm_hmma(
    const __half* __restrict__ A, const __half* __restrict__ W,
    const float* __restrict__ bias, void* __restrict__ Cv)
{
    __shared__ __align__(16) __half sA[128 * KSTR];
    __shared__ __align__(16) __half sW[128 * KSTR];

    const int tid  = threadIdx.x;
    const int warp = tid >> 5;
    const int lane = tid & 31;
    const int wm   = warp & 1;
    const int wn   = warp >> 1;
    const int m0   = blockIdx.y * 128;
    const int n0   = blockIdx.x * 128;

    const uint32_t sA_b = smem_u32(sA);
    const uint32_t sW_b = smem_u32(sW);

    float acc[4][4][4] = {};

    const int lrow = tid >> 1;
    const int lcol = (tid & 1) * 16;
    const uint32_t s_off = (uint32_t)(lrow * KSTR + lcol) * 2;

    const int fr = lane & 15;
    const int fc = (lane >> 4) * 8;
    const uint32_t a_off = (uint32_t)((wm * 64 + fr) * KSTR + fc) * 2;
    const uint32_t b_off = (uint32_t)((wn * 32 + fr) * KSTR + fc) * 2;

    for (int k0 = 0; k0 < DD; k0 += 32) {
        const size_t ga = (size_t)(m0 + lrow) * DD + k0 + lcol;
        const size_t gw = (size_t)(n0 + lrow) * DD + k0 + lcol;
        *(uint4*)((char*)sA + s_off)      = *(const uint4*)(A + ga);
        *(uint4*)((char*)sA + s_off + 16) = *(const uint4*)(A + ga + 8);
        *(uint4*)((char*)sW + s_off)      = *(const uint4*)(W + gw);
        *(uint4*)((char*)sW + s_off + 16) = *(const uint4*)(W + gw + 8);
        __syncthreads();

        #pragma unroll
        for (int ks = 0; ks < 2; ks++) {
            const uint32_t ko = (uint32_t)(ks * 16) * 2;
            uint32_t ah[4][4];
            #pragma unroll
            for (int im = 0; im < 4; im++) {
                const uint32_t ro = (uint32_t)(im * 16 * KSTR) * 2;
                ldmatrix_x4(ah[im], sA_b + a_off + ro + ko);
            }
            uint32_t bh[4][2];
            #pragma unroll
            for (int p = 0; p < 2; p++) {
                const uint32_t ro = (uint32_t)(p * 16 * KSTR) * 2;
                uint32_t t[4];
                ldmatrix_x4(t, sW_b + b_off + ro + ko);
                bh[2*p][0] = t[0]; bh[2*p][1] = t[2];
                bh[2*p+1][0] = t[1]; bh[2*p+1][1] = t[3];
            }
            #pragma unroll
            for (int im = 0; im < 4; im++)
                #pragma unroll
                for (int in = 0; in < 4; in++)
                    mma_f16(acc[im][in], ah[im], bh[in][0], bh[in][1]);
        }
        __syncthreads();
    }

    const int tr = lane >> 2;
    const int tc = (lane & 3) * 2;
    #pragma unroll
    for (int im = 0; im < 4; im++) {
        #pragma unroll
        for (int in = 0; in < 4; in++) {
            const int m = m0 + wm * 64 + im * 16 + tr;
            const int n = n0 + wn * 32 + in * 8 + tc;
            const float bx = bias[n], by = bias[n + 1];
            if (HALF_OUT) {
                __half* C = (__half*)Cv;
                __half2 v0 = __floats2half2_rn(acc[im][in][0] + bx, acc[im][in][1] + by);
                __half2 v1 = __floats2half2_rn(acc[im][in][2] + bx, acc[im][in][3] + by);
                *(__half2*)(C + (size_t)m * DD + n) = v0;
                *(__half2*)(C + (size_t)(m + 8) * DD + n) = v1;
            } else {
                float* C = (float*)Cv;
                float2 v0 = make_float2(acc[im][in][0] + bx, acc[im][in][1] + by);
                float2 v1 = make_float2(acc[im][in][2] + bx, acc[im][in][3] + by);
                *(float2*)(C + (size_t)m * DD + n) = v0;
                *(float2*)(C + (size_t)(m + 8) * DD + n) = v1;
            }
        }
    }
}

// ---------------------------------------------------------------------------
// HMMA flash attention (causal), all-fp16 operands.
// Block: 128 q x one (b,h); 8 warps x 16 q rows. K-tile = 64 keys.
// Q single fp16 in regs (scale applied to scores post-MMA, exact /8).
// K key-major smem (non-trans ldmatrix, pairing t0,t2/t1,t3).
// V key-major smem, PV B via ldmatrix.x4.TRANS (pairing t0,t1/t2,t3).
// Output written fp16 (feeds final GEMM directly).
// ---------------------------------------------------------------------------
#define QSTR 72

__global__ __launch_bounds__(256) void attn_hmma(
    const __half* __restrict__ Qp, const __half* __restrict__ Kp,
    const __half* __restrict__ Vp, __half* __restrict__ Op)
{
    __shared__ __align__(16) __half Ks[64 * QSTR];   // keys (key-major)
    __shared__ __align__(16) __half Vs[64 * QSTR];   // V    (key-major)

    const int tid  = threadIdx.x;
    const int warp = tid >> 5;
    const int lane = tid & 31;
    const int g    = lane >> 2;
    const int tg   = lane & 3;

    const int qb = gridDim.x - 1 - blockIdx.x;
    const int bh = blockIdx.y;
    const int b  = bh >> 4;
    const int h  = bh & 15;
    const size_t rowbase = (size_t)b * SS;
    const int col0 = h * DKK;

    const uint32_t Ks_b = smem_u32(Ks);
    const uint32_t Vs_b = smem_u32(Vs);

    const int fr  = lane & 15;
    const int fc8 = (lane >> 4) * 8;

    // ---- stage Q (128 x 64 fp16): rows 0-63 -> Ks, 64-127 -> Vs; 1 sync ----
    uint32_t qf[4][4];
    {
        const int row = tid >> 1;
        const int hc  = (tid & 1) * 32;
        const __half* src = Qp + (rowbase + (size_t)qb*128 + row) * DD + col0 + hc;
        __half* dst = (row < 64 ? Ks + row * QSTR : Vs + (row - 64) * QSTR) + hc;
        *(uint4*)(dst)      = *(const uint4*)(src);
        *(uint4*)(dst + 8)  = *(const uint4*)(src + 8);
        *(uint4*)(dst + 16) = *(const uint4*)(src + 16);
        *(uint4*)(dst + 24) = *(const uint4*)(src + 24);
        __syncthreads();
        const uint32_t base = (warp < 4) ? Ks_b : Vs_b;
        const uint32_t fo = (uint32_t)(((warp & 3)*16 + fr) * QSTR + fc8) * 2;
        #pragma unroll
        for (int kc = 0; kc < 4; kc++)
            ldmatrix_x4(qf[kc], base + fo + (uint32_t)(kc*16)*2);
        __syncthreads();
    }

    float m_run[2] = {-1e30f, -1e30f};
    float l_run[2] = {0.f, 0.f};
    float o[8][4] = {};

    const int kb_max = 2*qb + 1;
    for (int kb = 0; kb <= kb_max; kb++) {
        // ---- load K + V tiles (fp16, pure uint4 copies) ----
        {
            const int kr = tid >> 2;
            const int hc = (tid & 3) * 16;
            const size_t gsrc = (rowbase + (size_t)kb*64 + kr) * DD + col0 + hc;
            __half* kd = Ks + kr * QSTR + hc;
            __half* vd = Vs + kr * QSTR + hc;
            *(uint4*)(kd)     = *(const uint4*)(Kp + gsrc);
            *(uint4*)(kd + 8) = *(const uint4*)(Kp + gsrc + 8);
            *(uint4*)(vd)     = *(const uint4*)(Vp + gsrc);
            *(uint4*)(vd + 8) = *(const uint4*)(Vp + gsrc + 8);
        }
        __syncthreads();

        // ---- S = Q K^T ----
        float s[8][4] = {};
        #pragma unroll
        for (int kc = 0; kc < 4; kc++) {
            #pragma unroll
            for (int g2 = 0; g2 < 4; g2++) {
                uint32_t t[4];
                ldmatrix_x4(t, Ks_b + ((uint32_t)((g2*16 + fr) * QSTR + fc8) + kc*16) * 2);
                mma_f16(s[2*g2],   qf[kc], t[0], t[2]);
                mma_f16(s[2*g2+1], qf[kc], t[1], t[3]);
            }
        }

        // ---- scale + causal mask ----
        const int q0 = qb*128 + warp*16 + g;
        const bool edge = (kb*64 + 63 > q0);
        #pragma unroll
        for (int j = 0; j < 8; j++)
            #pragma unroll
            for (int e = 0; e < 4; e++) {
                s[j][e] *= 0.125f;
                if (edge) {
                    int kg = kb*64 + j*8 + tg*2 + (e & 1);
                    int qg = q0 + (e >> 1) * 8;
                    if (kg > qg) s[j][e] = -1e30f;
                }
            }

        // ---- online softmax ----
        float fac[2];
        #pragma unroll
        for (int hf = 0; hf < 2; hf++) {
            float tm = -1e30f;
            #pragma unroll
            for (int j = 0; j < 8; j++)
                tm = fmaxf(tm, fmaxf(s[j][2*hf], s[j][2*hf+1]));
            tm = fmaxf(tm, __shfl_xor_sync(0xffffffffu, tm, 1));
            tm = fmaxf(tm, __shfl_xor_sync(0xffffffffu, tm, 2));
            float mn = fmaxf(m_run[hf], tm);
            fac[hf]  = __expf(m_run[hf] - mn);
            m_run[hf] = mn;
            float rs = 0.f;
            #pragma unroll
            for (int j = 0; j < 8; j++) {
                float p0 = __expf(s[j][2*hf]   - mn);
                float p1 = __expf(s[j][2*hf+1] - mn);
                s[j][2*hf] = p0; s[j][2*hf+1] = p1;
                rs += p0 + p1;
            }
            rs += __shfl_xor_sync(0xffffffffu, rs, 1);
            rs += __shfl_xor_sync(0xffffffffu, rs, 2);
            l_run[hf] = l_run[hf] * fac[hf] + rs;
        }
        #pragma unroll
        for (int j = 0; j < 8; j++) {
            o[j][0] *= fac[0]; o[j][1] *= fac[0];
            o[j][2] *= fac[1]; o[j][3] *= fac[1];
        }

        // ---- O += P V  (V row-major, B-fragments via ldmatrix.trans) ----
        #pragma unroll
        for (int pk = 0; pk < 4; pk++) {
            uint32_t ap[4];
            __half2 h0 = __floats2half2_rn(s[2*pk][0],   s[2*pk][1]);
            __half2 h1 = __floats2half2_rn(s[2*pk][2],   s[2*pk][3]);
            __half2 h2 = __floats2half2_rn(s[2*pk+1][0], s[2*pk+1][1]);
            __half2 h3 = __floats2half2_rn(s[2*pk+1][2], s[2*pk+1][3]);
            ap[0] = *(uint32_t*)&h0; ap[1] = *(uint32_t*)&h1;
            ap[2] = *(uint32_t*)&h2; ap[3] = *(uint32_t*)&h3;
            #pragma unroll
            for (int g2 = 0; g2 < 4; g2++) {
                uint32_t t[4];
                ldmatrix_x4_trans(t, Vs_b +
                    ((uint32_t)((pk*16 + fr) * QSTR) + g2*16 + fc8) * 2);
                // trans pairing: t0,t1 = b0,b1 of n-tile0; t2,t3 of n-tile1
                mma_f16(o[2*g2],   ap, t[0], t[1]);
                mma_f16(o[2*g2+1], ap, t[2], t[3]);
            }
        }
        __syncthreads();
    }

    // ---- epilogue (fp16 out) ----
    const float inv0 = 1.f / l_run[0];
    const float inv1 = 1.f / l_run[1];
    const size_t q0 = rowbase + (size_t)qb*128 + warp*16 + g;
    #pragma unroll
    for (int j = 0; j < 8; j++) {
        const int d = col0 + j*8 + tg*2;
        *(__half2*)(Op + q0 * DD + d) =
            __floats2half2_rn(o[j][0]*inv0, o[j][1]*inv0);
        *(__half2*)(Op + (q0 + 8) * DD + d) =
            __floats2half2_rn(o[j][2]*inv1, o[j][3]*inv1);
    }
}

// ---------------------------------------------------------------------------
// Launch. Inputs (metadata order): q,k,v,mask,wq,bq,wk,bk,wv,bv,wo,bo
// No runtime API in here besides symbol lookups + launches (graph capture).
// ---------------------------------------------------------------------------
extern "C" void kernel_launch(void* const* d_in, const int* in_sizes, int n_in,
                              void* d_out, int out_size)
{
    const float* q  = (const float*)d_in[0];
    const float* k  = (const float*)d_in[1];
    const float* v  = (const float*)d_in[2];
    const float* wq = (const float*)d_in[4];
    const float* bq = (const float*)d_in[5];
    const float* wk = (const float*)d_in[6];
    const float* bk = (const float*)d_in[7];
    const float* wv = (const float*)d_in[8];
    const float* bv = (const float*)d_in[9];
    const float* wo = (const float*)d_in[10];
    const float* bo = (const float*)d_in[11];

    __half *in16, *p16;
    cudaGetSymbolAddress((void**)&in16, g_in16);
    cudaGetSymbolAddress((void**)&p16,  g_p16);

    const int nin4 = (int)(ELEMS_IN / 4);
    const int nw4  = (int)(ELEMS_W / 4);

    cvt_f16<<<nin4 / 256, 256>>>(q,  in16 + OFF_IQ, nin4);
    cvt_f16<<<nin4 / 256, 256>>>(k,  in16 + OFF_IK, nin4);
    cvt_f16<<<nin4 / 256, 256>>>(v,  in16 + OFF_IV, nin4);
    cvt_f16<<<nw4 / 256, 256>>>(wq, in16 + OFF_WQ, nw4);
    cvt_f16<<<nw4 / 256, 256>>>(wk, in16 + OFF_WK, nw4);
    cvt_f16<<<nw4 / 256, 256>>>(wv, in16 + OFF_WV, nw4);
    cvt_f16<<<nw4 / 256, 256>>>(wo, in16 + OFF_WO, nw4);

    dim3 gemmGrid(DD / 128, MM / 128);   // (8, 32)
    gemm_hmma<true><<<gemmGrid, 256>>>(in16 + OFF_IQ, in16 + OFF_WQ, bq, p16 + OFF_PQ);
    gemm_hmma<true><<<gemmGrid, 256>>>(in16 + OFF_IK, in16 + OFF_WK, bk, p16 + OFF_PK);
    gemm_hmma<true><<<gemmGrid, 256>>>(in16 + OFF_IV, in16 + OFF_WV, bv, p16 + OFF_PV);

    dim3 attnGrid(SS / 128, BB * HH);    // (16, 32)
    attn_hmma<<<attnGrid, 256>>>(p16 + OFF_PQ, p16 + OFF_PK, p16 + OFF_PV, p16 + OFF_PO);

    gemm_hmma<false><<<gemmGrid, 256>>>(p16 + OFF_PO, in16 + OFF_WO, bo, (float*)d_out);
}